// round 2
// baseline (speedup 1.0000x reference)
#include <cuda_runtime.h>
#include <math.h>

#define BB 2
#define SS 2048
#define DM 1024
#define NH 16
#define DH 64
#define FF 4096
#define MT (BB*SS)   // 4096 rows total

// ---------------- scratch (static __device__, no allocation) ----------------
__device__ float g_h1[MT*DM];     // LN1 output
__device__ float g_q[MT*DM];      // [b,h,s,e]
__device__ float g_k[MT*DM];
__device__ float g_v[MT*DM];
__device__ float g_cat[MT*DM];    // attention output, concat layout [b,s,h*64+e]
__device__ float g_attx[MT*DM];   // x + attn proj
__device__ float g_h2[MT*DM];     // LN2 output
__device__ float g_ff1[(size_t)MT*FF];

// ---------------- LayerNorm: one block per row of 1024 ----------------
__global__ void ln_kernel(const float* __restrict__ x, const float* __restrict__ w,
                          const float* __restrict__ b, float* __restrict__ out) {
    int row = blockIdx.x;
    int t = threadIdx.x;                       // 256 threads, 4 floats each
    const float4* xr = (const float4*)(x + (size_t)row * DM);
    float4 v = xr[t];
    float s  = v.x + v.y + v.z + v.w;
    float ss = v.x*v.x + v.y*v.y + v.z*v.z + v.w*v.w;
    #pragma unroll
    for (int o = 16; o; o >>= 1) {
        s  += __shfl_xor_sync(0xffffffffu, s,  o);
        ss += __shfl_xor_sync(0xffffffffu, ss, o);
    }
    __shared__ float red[2][8];
    __shared__ float stats[2];
    int lane = t & 31, wid = t >> 5;
    if (lane == 0) { red[0][wid] = s; red[1][wid] = ss; }
    __syncthreads();
    if (t == 0) {
        float S1 = 0.f, S2 = 0.f;
        #pragma unroll
        for (int i = 0; i < 8; i++) { S1 += red[0][i]; S2 += red[1][i]; }
        float mu  = S1 * (1.f / DM);
        float var = S2 * (1.f / DM) - mu * mu;
        stats[0] = mu;
        stats[1] = rsqrtf(var + 1e-5f);
    }
    __syncthreads();
    float mu = stats[0], rs = stats[1];
    float4 wv = ((const float4*)w)[t];
    float4 bv = ((const float4*)b)[t];
    float4 o4;
    o4.x = (v.x - mu) * rs * wv.x + bv.x;
    o4.y = (v.y - mu) * rs * wv.y + bv.y;
    o4.z = (v.z - mu) * rs * wv.z + bv.z;
    o4.w = (v.w - mu) * rs * wv.w + bv.w;
    ((float4*)(out + (size_t)row * DM))[t] = o4;
}

// ---------------- SGEMM 128x128x8, 256 threads, 8x8 per thread ----------------
// BMODE: 0 = B row-major [K,N]; 1 = headed weight [H, K, 64], col = h*64+e
// CMODE: 0 = C row-major [M,N]; 1 = scatter to [b,h,s,e] (q/k/v layout)
// EPI:   0 = none; 1 = +resid; 2 = +bias, exact GELU; 3 = +bias, +resid
template<int BMODE, int CMODE, int EPI>
__global__ void sgemm128(const float* __restrict__ A, const float* __restrict__ Bm,
                         float* __restrict__ C, int M, int N, int K,
                         const float* __restrict__ bias, const float* __restrict__ resid)
{
    __shared__ float As[8][128];
    __shared__ float Bs[8][128];
    int tid  = threadIdx.x;
    int row0 = blockIdx.y * 128;
    int n0   = blockIdx.x * 128;
    int ar = tid >> 1, ac = (tid & 1) * 4;
    int br = tid >> 5, bc = (tid & 31) * 4;
    const float* Aptr = A + (size_t)(row0 + ar) * K + ac;
    int ty = tid >> 4, tx = tid & 15;
    float acc[8][8];
    #pragma unroll
    for (int i = 0; i < 8; i++)
        #pragma unroll
        for (int j = 0; j < 8; j++) acc[i][j] = 0.f;

    for (int k0 = 0; k0 < K; k0 += 8) {
        float4 a4 = *(const float4*)(Aptr + k0);
        float4 b4;
        if (BMODE == 0) {
            b4 = *(const float4*)(Bm + (size_t)(k0 + br) * N + n0 + bc);
        } else {
            int n = n0 + bc;
            b4 = *(const float4*)(Bm + ((size_t)(n >> 6) * K + (k0 + br)) * 64 + (n & 63));
        }
        As[ac + 0][ar] = a4.x;
        As[ac + 1][ar] = a4.y;
        As[ac + 2][ar] = a4.z;
        As[ac + 3][ar] = a4.w;
        *(float4*)&Bs[br][bc] = b4;
        __syncthreads();
        #pragma unroll
        for (int k = 0; k < 8; k++) {
            float a[8], b[8];
            #pragma unroll
            for (int i = 0; i < 8; i++) a[i] = As[k][ty * 8 + i];
            #pragma unroll
            for (int j = 0; j < 8; j++) b[j] = Bs[k][tx * 8 + j];
            #pragma unroll
            for (int i = 0; i < 8; i++)
                #pragma unroll
                for (int j = 0; j < 8; j++) acc[i][j] += a[i] * b[j];
        }
        __syncthreads();
    }

    #pragma unroll
    for (int i = 0; i < 8; i++) {
        int r = row0 + ty * 8 + i;
        #pragma unroll
        for (int j = 0; j < 8; j++) {
            int c = n0 + tx * 8 + j;
            float v = acc[i][j];
            if (EPI == 2) { v += bias[c]; v = 0.5f * v * (1.f + erff(v * 0.70710678118f)); }
            if (EPI == 3) { v += bias[c]; }
            if (EPI == 1 || EPI == 3) v += resid[(size_t)r * N + c];
            if (CMODE == 0) {
                C[(size_t)r * N + c] = v;
            } else {
                int bidx = r >> 11, s = r & 2047, hh = c >> 6, e = c & 63;
                C[(((size_t)(bidx * NH + hh)) * SS + s) * 64 + e] = v;
            }
        }
    }
}

// ---------------- Causal flash attention: 64 queries/block, 64 threads ----------------
// Q,K,V in [b,h,s,e]; output written directly to concat layout [b, s, h*64+e].
__global__ void attn_kernel(const float* __restrict__ Q, const float* __restrict__ Kg,
                            const float* __restrict__ Vg, float* __restrict__ Out)
{
    __shared__ float KV[64][64];     // reused: K for pass1, V for pass2
    __shared__ float sc[64][65];     // padded scores, per-thread row
    int t  = threadIdx.x;            // query row within tile
    int qt = blockIdx.x;             // query tile (0..31)
    int bh = blockIdx.y;             // b*16+h
    int qi = qt * 64 + t;

    const float* qrow = Q + ((size_t)bh * SS + qi) * 64;
    float q[64];
    #pragma unroll
    for (int e = 0; e < 64; e += 4) {
        float4 f = *(const float4*)(qrow + e);
        q[e] = f.x; q[e+1] = f.y; q[e+2] = f.z; q[e+3] = f.w;
    }
    float acc[64];
    #pragma unroll
    for (int e = 0; e < 64; e++) acc[e] = 0.f;
    float m = -INFINITY, l = 0.f;

    for (int kt = 0; kt <= qt; kt++) {
        int k0 = kt * 64;
        // load K tile (wait for previous V reads)
        __syncthreads();
        const float* kb = Kg + ((size_t)bh * SS + k0) * 64;
        for (int i = t; i < 64 * 16; i += 64) {
            int r = i >> 4, c = (i & 15) << 2;
            *(float4*)&KV[r][c] = *(const float4*)(kb + r * 64 + c);
        }
        __syncthreads();

        float tmax = -INFINITY;
        for (int j = 0; j < 64; j++) {
            float s = 0.f;
            #pragma unroll
            for (int e = 0; e < 64; e++) s += q[e] * KV[j][e];
            s *= 0.125f;                       // 1/sqrt(64)
            if (k0 + j > qi) s = -INFINITY;    // causal
            sc[t][j] = s;
            tmax = fmaxf(tmax, s);
        }
        float nm   = fmaxf(m, tmax);
        float corr = __expf(m - nm);
        l *= corr;
        #pragma unroll
        for (int e = 0; e < 64; e++) acc[e] *= corr;

        // load V tile into same buffer
        __syncthreads();
        const float* vb = Vg + ((size_t)bh * SS + k0) * 64;
        for (int i = t; i < 64 * 16; i += 64) {
            int r = i >> 4, c = (i & 15) << 2;
            *(float4*)&KV[r][c] = *(const float4*)(vb + r * 64 + c);
        }
        __syncthreads();

        for (int j = 0; j < 64; j++) {
            float p = __expf(sc[t][j] - nm);
            l += p;
            #pragma unroll
            for (int e = 0; e < 64; e++) acc[e] += p * KV[j][e];
        }
        m = nm;
    }

    float inv = 1.f / l;
    int b = bh >> 4, hh = bh & 15;
    float* orow = Out + ((size_t)(b * SS + qi)) * DM + hh * 64;
    #pragma unroll
    for (int e = 0; e < 64; e += 4) {
        float4 f;
        f.x = acc[e] * inv; f.y = acc[e+1] * inv;
        f.z = acc[e+2] * inv; f.w = acc[e+3] * inv;
        *(float4*)(orow + e) = f;
    }
}

// ---------------- launch ----------------
extern "C" void kernel_launch(void* const* d_in, const int* in_sizes, int n_in,
                              void* d_out, int out_size) {
    const float* x    = (const float*)d_in[0];
    // d_in[1] = mask (tril ones) — causality handled analytically
    const float* Wq   = (const float*)d_in[2];
    const float* Wk   = (const float*)d_in[3];
    const float* Wv   = (const float*)d_in[4];
    const float* Wo   = (const float*)d_in[5];
    const float* ln1w = (const float*)d_in[6];
    const float* ln1b = (const float*)d_in[7];
    const float* ln2w = (const float*)d_in[8];
    const float* ln2b = (const float*)d_in[9];
    const float* W1   = (const float*)d_in[10];
    const float* b1   = (const float*)d_in[11];
    const float* W2   = (const float*)d_in[12];
    const float* b2   = (const float*)d_in[13];
    float* out = (float*)d_out;

    float *h1, *q, *k, *v, *cat, *attx, *h2, *ff1;
    cudaGetSymbolAddress((void**)&h1,   g_h1);
    cudaGetSymbolAddress((void**)&q,    g_q);
    cudaGetSymbolAddress((void**)&k,    g_k);
    cudaGetSymbolAddress((void**)&v,    g_v);
    cudaGetSymbolAddress((void**)&cat,  g_cat);
    cudaGetSymbolAddress((void**)&attx, g_attx);
    cudaGetSymbolAddress((void**)&h2,   g_h2);
    cudaGetSymbolAddress((void**)&ff1,  g_ff1);

    // 1. LN1
    ln_kernel<<<MT, 256>>>(x, ln1w, ln1b, h1);

    // 2-4. QKV projections (headed weight, scatter to [b,h,s,e])
    dim3 g1(DM / 128, MT / 128);   // (8, 32)
    sgemm128<1,1,0><<<g1, 256>>>(h1, Wq, q, MT, DM, DM, nullptr, nullptr);
    sgemm128<1,1,0><<<g1, 256>>>(h1, Wk, k, MT, DM, DM, nullptr, nullptr);
    sgemm128<1,1,0><<<g1, 256>>>(h1, Wv, v, MT, DM, DM, nullptr, nullptr);

    // 5. causal attention -> concat layout
    attn_kernel<<<dim3(SS / 64, BB * NH), 64>>>(q, k, v, cat);

    // 6. output projection + residual
    sgemm128<0,0,1><<<g1, 256>>>(cat, Wo, attx, MT, DM, DM, nullptr, x);

    // 7. LN2
    ln_kernel<<<MT, 256>>>(attx, ln2w, ln2b, h2);

    // 8. FFN1 + bias + exact GELU
    dim3 g2(FF / 128, MT / 128);   // (32, 32)
    sgemm128<0,0,2><<<g2, 256>>>(h2, W1, ff1, MT, FF, DM, b1, nullptr);

    // 9. FFN2 + bias + residual -> d_out
    sgemm128<0,0,3><<<g1, 256>>>(ff1, W2, out, MT, DM, FF, b2, attx);
}

// round 3
// speedup vs baseline: 1.0960x; 1.0960x over previous
#include <cuda_runtime.h>
#include <math.h>

#define BB 2
#define SS 2048
#define DM 1024
#define NH 16
#define DH 64
#define FF 4096
#define MT (BB*SS)   // 4096 rows total

// ---------------- packed f32x2 helpers ----------------
union F2U { unsigned long long u; float2 f; };

__device__ __forceinline__ void fma2(F2U& d, const F2U a, const F2U b) {
    asm("fma.rn.f32x2 %0, %1, %2, %0;" : "+l"(d.u) : "l"(a.u), "l"(b.u));
}

// ---------------- scratch (static __device__, no allocation) ----------------
__device__ float g_h1[MT*DM];     // LN1 output
__device__ float g_q[MT*DM];      // [b,h,s,e]
__device__ float g_k[MT*DM];
__device__ float g_v[MT*DM];
__device__ float g_cat[MT*DM];    // attention output, concat layout [b,s,h*64+e]
__device__ float g_attx[MT*DM];   // x + attn proj
__device__ float g_h2[MT*DM];     // LN2 output
__device__ float g_ff1[(size_t)MT*FF];

// ---------------- LayerNorm: one block per row of 1024 ----------------
__global__ void ln_kernel(const float* __restrict__ x, const float* __restrict__ w,
                          const float* __restrict__ b, float* __restrict__ out) {
    int row = blockIdx.x;
    int t = threadIdx.x;                       // 256 threads, 4 floats each
    const float4* xr = (const float4*)(x + (size_t)row * DM);
    float4 v = xr[t];
    float s  = v.x + v.y + v.z + v.w;
    float ss = v.x*v.x + v.y*v.y + v.z*v.z + v.w*v.w;
    #pragma unroll
    for (int o = 16; o; o >>= 1) {
        s  += __shfl_xor_sync(0xffffffffu, s,  o);
        ss += __shfl_xor_sync(0xffffffffu, ss, o);
    }
    __shared__ float red[2][8];
    __shared__ float stats[2];
    int lane = t & 31, wid = t >> 5;
    if (lane == 0) { red[0][wid] = s; red[1][wid] = ss; }
    __syncthreads();
    if (t == 0) {
        float S1 = 0.f, S2 = 0.f;
        #pragma unroll
        for (int i = 0; i < 8; i++) { S1 += red[0][i]; S2 += red[1][i]; }
        float mu  = S1 * (1.f / DM);
        float var = S2 * (1.f / DM) - mu * mu;
        stats[0] = mu;
        stats[1] = rsqrtf(var + 1e-5f);
    }
    __syncthreads();
    float mu = stats[0], rs = stats[1];
    float4 wv = ((const float4*)w)[t];
    float4 bv = ((const float4*)b)[t];
    float4 o4;
    o4.x = (v.x - mu) * rs * wv.x + bv.x;
    o4.y = (v.y - mu) * rs * wv.y + bv.y;
    o4.z = (v.z - mu) * rs * wv.z + bv.z;
    o4.w = (v.w - mu) * rs * wv.w + bv.w;
    ((float4*)(out + (size_t)row * DM))[t] = o4;
}

// ---------------- SGEMM 128x128x8, double-buffered, f32x2 core ----------------
// 256 threads, 8x8 per thread (accumulated as 4 i-pairs x 8 j in f32x2 regs).
// BMODE: 0 = B row-major [K,N]; 1 = headed weight [H, K, 64], col = h*64+e
// CMODE: 0 = C row-major [M,N]; 1 = scatter to [b,h,s,e] (q/k/v layout)
// EPI:   0 = none; 1 = +resid; 2 = +bias, exact GELU; 3 = +bias, +resid
template<int BMODE, int CMODE, int EPI>
__global__ __launch_bounds__(256, 2)
void sgemm128(const float* __restrict__ A, const float* __restrict__ Bm,
              float* __restrict__ C, int M, int N, int K,
              const float* __restrict__ bias, const float* __restrict__ resid)
{
    __shared__ __align__(16) float As[2][8][128];
    __shared__ __align__(16) float Bs[2][8][128];
    int tid  = threadIdx.x;
    int row0 = blockIdx.y * 128;
    int n0   = blockIdx.x * 128;
    int ar = tid >> 1, ac = (tid & 1) * 4;
    int br = tid >> 5, bc = (tid & 31) * 4;
    const float* Aptr = A + (size_t)(row0 + ar) * K + ac;
    int ty = tid >> 4, tx = tid & 15;

    F2U acc[4][8];
    #pragma unroll
    for (int i = 0; i < 4; i++)
        #pragma unroll
        for (int j = 0; j < 8; j++) acc[i][j].u = 0ull;

    // B tile load address helper
    auto bload = [&](int k0) -> float4 {
        if (BMODE == 0) {
            return *(const float4*)(Bm + (size_t)(k0 + br) * N + n0 + bc);
        } else {
            int n = n0 + bc;
            return *(const float4*)(Bm + ((size_t)(n >> 6) * K + (k0 + br)) * 64 + (n & 63));
        }
    };

    // preload tile 0
    {
        float4 a4 = *(const float4*)(Aptr);
        float4 b4 = bload(0);
        As[0][ac + 0][ar] = a4.x;
        As[0][ac + 1][ar] = a4.y;
        As[0][ac + 2][ar] = a4.z;
        As[0][ac + 3][ar] = a4.w;
        *(float4*)&Bs[0][br][bc] = b4;
    }
    __syncthreads();

    int cur = 0;
    int NT = K >> 3;
    for (int t = 0; t < NT; t++) {
        float4 na, nb;
        bool more = (t + 1 < NT);
        if (more) {
            na = *(const float4*)(Aptr + (size_t)(t + 1) * 8);
            nb = bload((t + 1) * 8);
        }
        #pragma unroll
        for (int k = 0; k < 8; k++) {
            ulonglong2 A01 = *(const ulonglong2*)&As[cur][k][ty * 8];
            ulonglong2 A23 = *(const ulonglong2*)&As[cur][k][ty * 8 + 4];
            F2U ap[4];
            ap[0].u = A01.x; ap[1].u = A01.y;
            ap[2].u = A23.x; ap[3].u = A23.y;
            float4 b0 = *(const float4*)&Bs[cur][k][tx * 8];
            float4 b1 = *(const float4*)&Bs[cur][k][tx * 8 + 4];
            float bb[8] = {b0.x, b0.y, b0.z, b0.w, b1.x, b1.y, b1.z, b1.w};
            #pragma unroll
            for (int j = 0; j < 8; j++) {
                F2U bd; bd.f = make_float2(bb[j], bb[j]);
                #pragma unroll
                for (int ip = 0; ip < 4; ip++) fma2(acc[ip][j], ap[ip], bd);
            }
        }
        if (more) {
            int nxt = cur ^ 1;
            As[nxt][ac + 0][ar] = na.x;
            As[nxt][ac + 1][ar] = na.y;
            As[nxt][ac + 2][ar] = na.z;
            As[nxt][ac + 3][ar] = na.w;
            *(float4*)&Bs[nxt][br][bc] = nb;
            __syncthreads();
            cur = nxt;
        }
    }

    #pragma unroll
    for (int ip = 0; ip < 4; ip++) {
        #pragma unroll
        for (int half = 0; half < 2; half++) {
            int r = row0 + ty * 8 + 2 * ip + half;
            #pragma unroll
            for (int j = 0; j < 8; j++) {
                int c = n0 + tx * 8 + j;
                float v = half ? acc[ip][j].f.y : acc[ip][j].f.x;
                if (EPI == 2) { v += bias[c]; v = 0.5f * v * (1.f + erff(v * 0.70710678118f)); }
                if (EPI == 3) { v += bias[c]; }
                if (EPI == 1 || EPI == 3) v += resid[(size_t)r * N + c];
                if (CMODE == 0) {
                    C[(size_t)r * N + c] = v;
                } else {
                    int bidx = r >> 11, s = r & 2047, hh = c >> 6, e = c & 63;
                    C[(((size_t)(bidx * NH + hh)) * SS + s) * 64 + e] = v;
                }
            }
        }
    }
}

// ---------------- Causal flash attention: 64 queries/block, 64 threads ----------------
// Q,K,V in [b,h,s,e]; output written directly to concat layout [b, s, h*64+e].
// Inner loops in packed f32x2.
__global__ void attn_kernel(const float* __restrict__ Q, const float* __restrict__ Kg,
                            const float* __restrict__ Vg, float* __restrict__ Out)
{
    __shared__ __align__(16) float KV[64][64];  // reused: K pass1, V pass2
    __shared__ float sc[64][65];                // padded scores, per-thread row
    int t  = threadIdx.x;            // query row within tile
    int qt = blockIdx.x;             // query tile (0..31)
    int bh = blockIdx.y;             // b*16+h
    int qi = qt * 64 + t;

    const float* qrow = Q + ((size_t)bh * SS + qi) * 64;
    F2U qp[32];
    #pragma unroll
    for (int e = 0; e < 32; e += 2) {
        float4 f = *(const float4*)(qrow + 2 * e);
        qp[e].f     = make_float2(f.x, f.y);
        qp[e + 1].f = make_float2(f.z, f.w);
    }
    F2U accp[32];
    #pragma unroll
    for (int e = 0; e < 32; e++) accp[e].u = 0ull;
    float m = -INFINITY, l = 0.f;

    for (int kt = 0; kt <= qt; kt++) {
        int k0 = kt * 64;
        // load K tile (wait for previous V reads)
        __syncthreads();
        const float* kb = Kg + ((size_t)bh * SS + k0) * 64;
        for (int i = t; i < 64 * 16; i += 64) {
            int r = i >> 4, c = (i & 15) << 2;
            *(float4*)&KV[r][c] = *(const float4*)(kb + r * 64 + c);
        }
        __syncthreads();

        float tmax = -INFINITY;
        for (int j = 0; j < 64; j++) {
            const F2U* kr = (const F2U*)KV[j];
            F2U s2; s2.u = 0ull;
            #pragma unroll
            for (int e = 0; e < 32; e++) fma2(s2, qp[e], kr[e]);
            float s = (s2.f.x + s2.f.y) * 0.125f;   // 1/sqrt(64)
            if (k0 + j > qi) s = -INFINITY;          // causal
            sc[t][j] = s;
            tmax = fmaxf(tmax, s);
        }
        float nm   = fmaxf(m, tmax);
        float corr = __expf(m - nm);
        l *= corr;
        {
            F2U cd; cd.f = make_float2(corr, corr);
            #pragma unroll
            for (int e = 0; e < 32; e++) {
                accp[e].f.x *= corr;
                accp[e].f.y *= corr;
            }
            (void)cd;
        }

        // load V tile into same buffer
        __syncthreads();
        const float* vb = Vg + ((size_t)bh * SS + k0) * 64;
        for (int i = t; i < 64 * 16; i += 64) {
            int r = i >> 4, c = (i & 15) << 2;
            *(float4*)&KV[r][c] = *(const float4*)(vb + r * 64 + c);
        }
        __syncthreads();

        for (int j = 0; j < 64; j++) {
            float p = __expf(sc[t][j] - nm);
            l += p;
            F2U pd; pd.f = make_float2(p, p);
            const F2U* vr = (const F2U*)KV[j];
            #pragma unroll
            for (int e = 0; e < 32; e++) fma2(accp[e], pd, vr[e]);
        }
        m = nm;
    }

    float inv = 1.f / l;
    int b = bh >> 4, hh = bh & 15;
    float* orow = Out + ((size_t)(b * SS + qi)) * DM + hh * 64;
    #pragma unroll
    for (int e = 0; e < 32; e += 2) {
        float4 f;
        f.x = accp[e].f.x * inv;     f.y = accp[e].f.y * inv;
        f.z = accp[e + 1].f.x * inv; f.w = accp[e + 1].f.y * inv;
        *(float4*)(orow + 2 * e) = f;
    }
}

// ---------------- launch ----------------
extern "C" void kernel_launch(void* const* d_in, const int* in_sizes, int n_in,
                              void* d_out, int out_size) {
    const float* x    = (const float*)d_in[0];
    // d_in[1] = mask (tril ones) — causality handled analytically
    const float* Wq   = (const float*)d_in[2];
    const float* Wk   = (const float*)d_in[3];
    const float* Wv   = (const float*)d_in[4];
    const float* Wo   = (const float*)d_in[5];
    const float* ln1w = (const float*)d_in[6];
    const float* ln1b = (const float*)d_in[7];
    const float* ln2w = (const float*)d_in[8];
    const float* ln2b = (const float*)d_in[9];
    const float* W1   = (const float*)d_in[10];
    const float* b1   = (const float*)d_in[11];
    const float* W2   = (const float*)d_in[12];
    const float* b2   = (const float*)d_in[13];
    float* out = (float*)d_out;

    float *h1, *q, *k, *v, *cat, *attx, *h2, *ff1;
    cudaGetSymbolAddress((void**)&h1,   g_h1);
    cudaGetSymbolAddress((void**)&q,    g_q);
    cudaGetSymbolAddress((void**)&k,    g_k);
    cudaGetSymbolAddress((void**)&v,    g_v);
    cudaGetSymbolAddress((void**)&cat,  g_cat);
    cudaGetSymbolAddress((void**)&attx, g_attx);
    cudaGetSymbolAddress((void**)&h2,   g_h2);
    cudaGetSymbolAddress((void**)&ff1,  g_ff1);

    // 1. LN1
    ln_kernel<<<MT, 256>>>(x, ln1w, ln1b, h1);

    // 2-4. QKV projections (headed weight, scatter to [b,h,s,e])
    dim3 g1(DM / 128, MT / 128);   // (8, 32)
    sgemm128<1,1,0><<<g1, 256>>>(h1, Wq, q, MT, DM, DM, nullptr, nullptr);
    sgemm128<1,1,0><<<g1, 256>>>(h1, Wk, k, MT, DM, DM, nullptr, nullptr);
    sgemm128<1,1,0><<<g1, 256>>>(h1, Wv, v, MT, DM, DM, nullptr, nullptr);

    // 5. causal attention -> concat layout
    attn_kernel<<<dim3(SS / 64, BB * NH), 64>>>(q, k, v, cat);

    // 6. output projection + residual
    sgemm128<0,0,1><<<g1, 256>>>(cat, Wo, attx, MT, DM, DM, nullptr, x);

    // 7. LN2
    ln_kernel<<<MT, 256>>>(attx, ln2w, ln2b, h2);

    // 8. FFN1 + bias + exact GELU
    dim3 g2(FF / 128, MT / 128);   // (32, 32)
    sgemm128<0,0,2><<<g2, 256>>>(h2, W1, ff1, MT, FF, DM, b1, nullptr);

    // 9. FFN2 + bias + residual -> d_out
    sgemm128<0,0,3><<<g1, 256>>>(ff1, W2, out, MT, DM, FF, b2, attx);
}

// round 6
// speedup vs baseline: 1.6457x; 1.5015x over previous
#include <cuda_runtime.h>
#include <cuda_bf16.h>
#include <mma.h>
#include <math.h>
#include <stdint.h>

typedef __nv_bfloat16 bf16;
using namespace nvcuda;

#define BB 2
#define SS 2048
#define DM 1024
#define NH 16
#define FF 4096
#define MT (BB*SS)   // 4096 rows

// ===================== packed f32x2 helpers (attention) =====================
union F2U { unsigned long long u; float2 f; };
__device__ __forceinline__ void fma2(F2U& d, const F2U a, const F2U b) {
    asm("fma.rn.f32x2 %0, %1, %2, %0;" : "+l"(d.u) : "l"(a.u), "l"(b.u));
}

// ===================== split helpers =====================
__device__ __forceinline__ void split2(float v, bf16& h, bf16& l) {
    h = __float2bfloat16(v);
    l = __float2bfloat16(v - __bfloat162float(h));
}
__device__ __forceinline__ uint32_t pkb(bf16 a, bf16 b) {
    unsigned short ua = __bfloat16_as_ushort(a), ub = __bfloat16_as_ushort(b);
    return (uint32_t)ua | ((uint32_t)ub << 16);
}

__device__ __forceinline__ uint32_t smem_to_u32(const void* p) {
    uint32_t a;
    asm("{ .reg .u64 tmp; cvta.to.shared.u64 tmp, %1; cvt.u32.u64 %0, tmp; }" : "=r"(a) : "l"(p));
    return a;
}
#define CP_ASYNC16(dst, src) \
    asm volatile("cp.async.cg.shared.global [%0], [%1], 16;" :: "r"(dst), "l"(src))
#define CP_COMMIT() asm volatile("cp.async.commit_group;" ::: "memory")
#define CP_WAIT1()  asm volatile("cp.async.wait_group 1;"  ::: "memory")
#define CP_WAIT0()  asm volatile("cp.async.wait_group 0;"  ::: "memory")

// ===================== scratch =====================
__device__ bf16 g_h1a[MT*DM],  g_h1b[MT*DM];
__device__ float g_q[MT*DM], g_k[MT*DM], g_v[MT*DM];
__device__ bf16 g_cata[MT*DM], g_catb[MT*DM];
__device__ float g_attx[MT*DM];
__device__ bf16 g_h2a[MT*DM],  g_h2b[MT*DM];
__device__ bf16 g_ff1a[(size_t)MT*FF], g_ff1b[(size_t)MT*FF];
__device__ bf16 g_Wqkva[3*DM*DM], g_Wqkvb[3*DM*DM];
__device__ bf16 g_Woa[DM*DM],  g_Wob[DM*DM];
__device__ bf16 g_W1a[DM*FF],  g_W1b[DM*FF];
__device__ bf16 g_W2a[DM*FF],  g_W2b[DM*FF];

// ===================== LayerNorm -> bf16 split pair =====================
__global__ void ln_split_kernel(const float* __restrict__ x, const float* __restrict__ w,
                                const float* __restrict__ b, bf16* __restrict__ o0, bf16* __restrict__ o1) {
    int row = blockIdx.x;
    int t = threadIdx.x;                       // 256 threads x 4 floats
    const float4* xr = (const float4*)(x + (size_t)row * DM);
    float4 v = xr[t];
    float s  = v.x + v.y + v.z + v.w;
    float ss = v.x*v.x + v.y*v.y + v.z*v.z + v.w*v.w;
    #pragma unroll
    for (int o = 16; o; o >>= 1) {
        s  += __shfl_xor_sync(0xffffffffu, s,  o);
        ss += __shfl_xor_sync(0xffffffffu, ss, o);
    }
    __shared__ float red[2][8];
    __shared__ float stats[2];
    int lane = t & 31, wid = t >> 5;
    if (lane == 0) { red[0][wid] = s; red[1][wid] = ss; }
    __syncthreads();
    if (t == 0) {
        float S1 = 0.f, S2 = 0.f;
        #pragma unroll
        for (int i = 0; i < 8; i++) { S1 += red[0][i]; S2 += red[1][i]; }
        float mu  = S1 * (1.f / DM);
        float var = S2 * (1.f / DM) - mu * mu;
        stats[0] = mu; stats[1] = rsqrtf(var + 1e-5f);
    }
    __syncthreads();
    float mu = stats[0], rs = stats[1];
    float4 wv = ((const float4*)w)[t];
    float4 bv = ((const float4*)b)[t];
    float y0 = (v.x - mu) * rs * wv.x + bv.x;
    float y1 = (v.y - mu) * rs * wv.y + bv.y;
    float y2 = (v.z - mu) * rs * wv.z + bv.z;
    float y3 = (v.w - mu) * rs * wv.w + bv.w;
    bf16 h0,l0,h1,l1,h2,l2,h3,l3;
    split2(y0,h0,l0); split2(y1,h1,l1); split2(y2,h2,l2); split2(y3,h3,l3);
    size_t idx = (size_t)row * DM + t * 4;
    *(uint2*)(o0 + idx) = make_uint2(pkb(h0,h1), pkb(h2,h3));
    *(uint2*)(o1 + idx) = make_uint2(pkb(l0,l1), pkb(l2,l3));
}

// ===================== transpose + split: out[c][r] = in[r][c] (bf16 hi/lo) =====================
__global__ void tsplit_kernel(const float* __restrict__ in, bf16* __restrict__ o0, bf16* __restrict__ o1,
                              int R, int C, size_t inBatch, size_t outBatch) {
    in += (size_t)blockIdx.z * inBatch;
    o0 += (size_t)blockIdx.z * outBatch;
    o1 += (size_t)blockIdx.z * outBatch;
    __shared__ float tile[32][33];
    int c0 = blockIdx.x * 32, r0 = blockIdx.y * 32;
    int tx = threadIdx.x, ty = threadIdx.y;   // (32, 8)
    #pragma unroll
    for (int i = 0; i < 4; i++)
        tile[ty + 8*i][tx] = in[(size_t)(r0 + ty + 8*i) * C + c0 + tx];
    __syncthreads();
    #pragma unroll
    for (int i = 0; i < 4; i++) {
        float v = tile[tx][ty + 8*i];
        bf16 h, l; split2(v, h, l);
        size_t oi = (size_t)(c0 + ty + 8*i) * R + r0 + tx;
        o0[oi] = h; o1[oi] = l;
    }
}

// ===================== wmma split-bf16 GEMM =====================
// D[M,N] = (A0+A1)(B0+B1)^T ~= A0B0 + A0B1 + A1B0, fp32 accum.
// A row-major [M,K] bf16; B row-major [N,K] bf16 (i.e. col-major KxN).
// CTA tile 128x128, 8 warps of 32x64, BK=32, 3-stage cp.async pipeline.
// EPI: 0 = QKV scatter -> q/k/v [b,h,s,e] fp32
//      1 = +resid -> fp32 row-major
//      2 = +bias, exact GELU -> bf16 split pair
//      3 = +bias, +resid -> fp32 row-major
#define TILEB   10240              // one 128x32 bf16 tile, row pitch 80B
#define STAGEB  (4*TILEB)          // A0,A1,B0,B1
#define GSMEM   (3*STAGEB)         // 122880 B  (>= 128*132*4 = 67584 epilogue)

template<int EPI>
__global__ __launch_bounds__(256, 1)
void gemmw(const bf16* __restrict__ A0, const bf16* __restrict__ A1,
           const bf16* __restrict__ B0, const bf16* __restrict__ B1, int K,
           float* __restrict__ out0, float* __restrict__ out1, float* __restrict__ out2,
           bf16* __restrict__ s0, bf16* __restrict__ s1,
           const float* __restrict__ bias, const float* __restrict__ resid, int N)
{
    extern __shared__ __align__(16) uint8_t smraw[];
    const uint32_t smb = smem_to_u32(smraw);
    const int tid = threadIdx.x;
    const int wid = tid >> 5;
    const int wm = wid >> 1, wn = wid & 1;     // 4 x 2 warp grid
    const int m0 = blockIdx.y * 128;
    const int n0 = blockIdx.x * 128;

    const bf16* gsrc[4] = { A0 + (size_t)m0 * K, A1 + (size_t)m0 * K,
                            B0 + (size_t)n0 * K, B1 + (size_t)n0 * K };

    wmma::fragment<wmma::accumulator, 16, 16, 16, float> acc[2][4];
    #pragma unroll
    for (int i = 0; i < 2; i++)
        #pragma unroll
        for (int j = 0; j < 4; j++) wmma::fill_fragment(acc[i][j], 0.0f);

    const int NCH = K >> 5;

    // async load of chunk ch into stage st
    auto issue = [&](int ch, int st) {
        int k0 = ch << 5;
        #pragma unroll
        for (int i = 0; i < 8; i++) {
            int idx = i * 256 + tid;
            int t4  = idx >> 9;
            int rem = idx & 511;
            int row = rem >> 2;
            int cch = rem & 3;
            uint32_t dst = smb + st * STAGEB + t4 * TILEB + row * 80 + cch * 16;
            const bf16* src = gsrc[t4] + (size_t)row * K + k0 + cch * 8;
            CP_ASYNC16(dst, src);
        }
        CP_COMMIT();
    };

    issue(0, 0);
    if (NCH > 1) issue(1, 1);

    for (int ch = 0; ch < NCH; ch++) {
        if (ch == NCH - 1) { CP_WAIT0(); } else { CP_WAIT1(); }
        __syncthreads();
        const int st = ch % 3;
        const bf16* As0 = (const bf16*)(smraw + st * STAGEB);
        const bf16* As1 = (const bf16*)(smraw + st * STAGEB + TILEB);
        const bf16* Bs0 = (const bf16*)(smraw + st * STAGEB + 2 * TILEB);
        const bf16* Bs1 = (const bf16*)(smraw + st * STAGEB + 3 * TILEB);
        #pragma unroll
        for (int kk = 0; kk < 32; kk += 16) {
            wmma::fragment<wmma::matrix_a, 16, 16, 16, bf16, wmma::row_major> a0[2], a1[2];
            #pragma unroll
            for (int i = 0; i < 2; i++) {
                wmma::load_matrix_sync(a0[i], As0 + (wm * 32 + i * 16) * 40 + kk, 40);
                wmma::load_matrix_sync(a1[i], As1 + (wm * 32 + i * 16) * 40 + kk, 40);
            }
            #pragma unroll
            for (int j = 0; j < 4; j++) {
                wmma::fragment<wmma::matrix_b, 16, 16, 16, bf16, wmma::col_major> b0, b1;
                wmma::load_matrix_sync(b0, Bs0 + (wn * 64 + j * 16) * 40 + kk, 40);
                wmma::load_matrix_sync(b1, Bs1 + (wn * 64 + j * 16) * 40 + kk, 40);
                #pragma unroll
                for (int i = 0; i < 2; i++) {
                    wmma::mma_sync(acc[i][j], a0[i], b0, acc[i][j]);
                    wmma::mma_sync(acc[i][j], a0[i], b1, acc[i][j]);
                    wmma::mma_sync(acc[i][j], a1[i], b0, acc[i][j]);
                }
            }
        }
        __syncthreads();
        if (ch + 2 < NCH) issue(ch + 2, (ch + 2) % 3);
    }

    // ---- epilogue through smem for coalesced writes ----
    __syncthreads();
    float* Cs = (float*)smraw;        // [128][132]
    #pragma unroll
    for (int i = 0; i < 2; i++)
        #pragma unroll
        for (int j = 0; j < 4; j++)
            wmma::store_matrix_sync(Cs + (wm * 32 + i * 16) * 132 + (wn * 64 + j * 16),
                                    acc[i][j], 132, wmma::mem_row_major);
    __syncthreads();

    #pragma unroll
    for (int it = 0; it < 16; it++) {
        int idx = it * 256 + tid;
        int r  = idx >> 5;
        int c4 = (idx & 31) << 2;
        float4 vv = *(const float4*)(Cs + r * 132 + c4);
        int row = m0 + r;
        int c   = n0 + c4;
        if (EPI == 0) {
            int b = row >> 11, sq = row & 2047;
            int proj = c >> 10, cc = c & 1023, hh = cc >> 6, e0 = cc & 63;
            float* base = (proj == 0) ? out0 : (proj == 1) ? out1 : out2;
            *(float4*)(base + ((size_t)(b * NH + hh) * SS + sq) * 64 + e0) = vv;
        } else if (EPI == 1) {
            float4 r4 = *(const float4*)(resid + (size_t)row * N + c);
            vv.x += r4.x; vv.y += r4.y; vv.z += r4.z; vv.w += r4.w;
            *(float4*)(out0 + (size_t)row * N + c) = vv;
        } else if (EPI == 2) {
            float4 b4 = *(const float4*)(bias + c);
            float o[4] = {vv.x + b4.x, vv.y + b4.y, vv.z + b4.z, vv.w + b4.w};
            #pragma unroll
            for (int u = 0; u < 4; u++) o[u] = 0.5f * o[u] * (1.f + erff(o[u] * 0.70710678118f));
            bf16 h0,l0,h1,l1,h2,l2,h3,l3;
            split2(o[0],h0,l0); split2(o[1],h1,l1); split2(o[2],h2,l2); split2(o[3],h3,l3);
            size_t base = (size_t)row * N + c;
            *(uint2*)(s0 + base) = make_uint2(pkb(h0,h1), pkb(h2,h3));
            *(uint2*)(s1 + base) = make_uint2(pkb(l0,l1), pkb(l2,l3));
        } else {  // EPI == 3
            float4 b4 = *(const float4*)(bias + c);
            float4 r4 = *(const float4*)(resid + (size_t)row * N + c);
            vv.x += b4.x + r4.x; vv.y += b4.y + r4.y;
            vv.z += b4.z + r4.z; vv.w += b4.w + r4.w;
            *(float4*)(out0 + (size_t)row * N + c) = vv;
        }
    }
}

// ===================== causal flash attention (fp32, f32x2), writes bf16 split concat =====================
__global__ void attn_kernel(const float* __restrict__ Q, const float* __restrict__ Kg,
                            const float* __restrict__ Vg,
                            bf16* __restrict__ O0, bf16* __restrict__ O1)
{
    __shared__ __align__(16) float KV[64][64];
    __shared__ float sc[64][65];
    int t  = threadIdx.x;
    int qt = blockIdx.x;
    int bh = blockIdx.y;
    int qi = qt * 64 + t;

    const float* qrow = Q + ((size_t)bh * SS + qi) * 64;
    F2U qp[32];
    #pragma unroll
    for (int e = 0; e < 32; e += 2) {
        float4 f = *(const float4*)(qrow + 2 * e);
        qp[e].f     = make_float2(f.x, f.y);
        qp[e + 1].f = make_float2(f.z, f.w);
    }
    F2U accp[32];
    #pragma unroll
    for (int e = 0; e < 32; e++) accp[e].u = 0ull;
    float m = -INFINITY, l = 0.f;

    for (int kt = 0; kt <= qt; kt++) {
        int k0 = kt * 64;
        __syncthreads();
        const float* kb = Kg + ((size_t)bh * SS + k0) * 64;
        for (int i = t; i < 64 * 16; i += 64) {
            int r = i >> 4, c = (i & 15) << 2;
            *(float4*)&KV[r][c] = *(const float4*)(kb + r * 64 + c);
        }
        __syncthreads();

        float tmax = -INFINITY;
        for (int j = 0; j < 64; j++) {
            const F2U* kr = (const F2U*)KV[j];
            F2U s2; s2.u = 0ull;
            #pragma unroll
            for (int e = 0; e < 32; e++) fma2(s2, qp[e], kr[e]);
            float s = (s2.f.x + s2.f.y) * 0.125f;
            if (k0 + j > qi) s = -INFINITY;
            sc[t][j] = s;
            tmax = fmaxf(tmax, s);
        }
        float nm   = fmaxf(m, tmax);
        float corr = __expf(m - nm);
        l *= corr;
        #pragma unroll
        for (int e = 0; e < 32; e++) { accp[e].f.x *= corr; accp[e].f.y *= corr; }

        __syncthreads();
        const float* vb = Vg + ((size_t)bh * SS + k0) * 64;
        for (int i = t; i < 64 * 16; i += 64) {
            int r = i >> 4, c = (i & 15) << 2;
            *(float4*)&KV[r][c] = *(const float4*)(vb + r * 64 + c);
        }
        __syncthreads();

        for (int j = 0; j < 64; j++) {
            float p = __expf(sc[t][j] - nm);
            l += p;
            F2U pd; pd.f = make_float2(p, p);
            const F2U* vr = (const F2U*)KV[j];
            #pragma unroll
            for (int e = 0; e < 32; e++) fma2(accp[e], pd, vr[e]);
        }
        m = nm;
    }

    float inv = 1.f / l;
    int b = bh >> 4, hh = bh & 15;
    size_t base = ((size_t)(b * SS + qi)) * DM + hh * 64;
    #pragma unroll
    for (int e = 0; e < 32; e++) {
        float v0 = accp[e].f.x * inv, v1 = accp[e].f.y * inv;
        bf16 h0,l0,h1,l1;
        split2(v0,h0,l0); split2(v1,h1,l1);
        *(uint32_t*)(O0 + base + 2*e) = pkb(h0,h1);
        *(uint32_t*)(O1 + base + 2*e) = pkb(l0,l1);
    }
}

// ===================== launch =====================
extern "C" void kernel_launch(void* const* d_in, const int* in_sizes, int n_in,
                              void* d_out, int out_size) {
    const float* x    = (const float*)d_in[0];
    const float* Wq   = (const float*)d_in[2];
    const float* Wk   = (const float*)d_in[3];
    const float* Wv   = (const float*)d_in[4];
    const float* Wo   = (const float*)d_in[5];
    const float* ln1w = (const float*)d_in[6];
    const float* ln1b = (const float*)d_in[7];
    const float* ln2w = (const float*)d_in[8];
    const float* ln2b = (const float*)d_in[9];
    const float* W1   = (const float*)d_in[10];
    const float* b1   = (const float*)d_in[11];
    const float* W2   = (const float*)d_in[12];
    const float* b2   = (const float*)d_in[13];
    float* out = (float*)d_out;

    bf16 *h1a,*h1b,*cata,*catb,*h2a,*h2b,*ff1a,*ff1b;
    bf16 *wqkva,*wqkvb,*woa,*wob,*w1a,*w1b,*w2a,*w2b;
    float *q,*k,*v,*attx;
    cudaGetSymbolAddress((void**)&h1a, g_h1a);   cudaGetSymbolAddress((void**)&h1b, g_h1b);
    cudaGetSymbolAddress((void**)&q, g_q);       cudaGetSymbolAddress((void**)&k, g_k);
    cudaGetSymbolAddress((void**)&v, g_v);
    cudaGetSymbolAddress((void**)&cata, g_cata); cudaGetSymbolAddress((void**)&catb, g_catb);
    cudaGetSymbolAddress((void**)&attx, g_attx);
    cudaGetSymbolAddress((void**)&h2a, g_h2a);   cudaGetSymbolAddress((void**)&h2b, g_h2b);
    cudaGetSymbolAddress((void**)&ff1a, g_ff1a); cudaGetSymbolAddress((void**)&ff1b, g_ff1b);
    cudaGetSymbolAddress((void**)&wqkva, g_Wqkva); cudaGetSymbolAddress((void**)&wqkvb, g_Wqkvb);
    cudaGetSymbolAddress((void**)&woa, g_Woa);   cudaGetSymbolAddress((void**)&wob, g_Wob);
    cudaGetSymbolAddress((void**)&w1a, g_W1a);   cudaGetSymbolAddress((void**)&w1b, g_W1b);
    cudaGetSymbolAddress((void**)&w2a, g_W2a);   cudaGetSymbolAddress((void**)&w2b, g_W2b);

    cudaFuncSetAttribute(gemmw<0>, cudaFuncAttributeMaxDynamicSharedMemorySize, GSMEM);
    cudaFuncSetAttribute(gemmw<1>, cudaFuncAttributeMaxDynamicSharedMemorySize, GSMEM);
    cudaFuncSetAttribute(gemmw<2>, cudaFuncAttributeMaxDynamicSharedMemorySize, GSMEM);
    cudaFuncSetAttribute(gemmw<3>, cudaFuncAttributeMaxDynamicSharedMemorySize, GSMEM);

    dim3 t32x8(32, 8);

    // LN1 -> h1 splits
    ln_split_kernel<<<MT, 256>>>(x, ln1w, ln1b, h1a, h1b);

    // weight transpose + split (B layout: [N,K] bf16 hi/lo)
    tsplit_kernel<<<dim3(2, 32, 16), t32x8>>>(Wq, wqkva,               wqkvb,               1024, 64, (size_t)1024*64, (size_t)64*1024);
    tsplit_kernel<<<dim3(2, 32, 16), t32x8>>>(Wk, wqkva + 1024*1024,   wqkvb + 1024*1024,   1024, 64, (size_t)1024*64, (size_t)64*1024);
    tsplit_kernel<<<dim3(2, 32, 16), t32x8>>>(Wv, wqkva + 2*1024*1024, wqkvb + 2*1024*1024, 1024, 64, (size_t)1024*64, (size_t)64*1024);
    tsplit_kernel<<<dim3(32, 32, 1),  t32x8>>>(Wo, woa, wob, 1024, 1024, 0, 0);
    tsplit_kernel<<<dim3(128, 32, 1), t32x8>>>(W1, w1a, w1b, 1024, 4096, 0, 0);
    tsplit_kernel<<<dim3(32, 128, 1), t32x8>>>(W2, w2a, w2b, 4096, 1024, 0, 0);

    // QKV fused GEMM: M=4096, N=3072, K=1024 -> q/k/v fp32 [b,h,s,e]
    gemmw<0><<<dim3(24, 32), 256, GSMEM>>>(h1a, h1b, wqkva, wqkvb, 1024,
                                           q, k, v, nullptr, nullptr, nullptr, nullptr, 0);

    // causal attention -> concat bf16 splits
    attn_kernel<<<dim3(SS / 64, BB * NH), 64>>>(q, k, v, cata, catb);

    // Wo + residual(x) -> attx fp32
    gemmw<1><<<dim3(8, 32), 256, GSMEM>>>(cata, catb, woa, wob, 1024,
                                          attx, nullptr, nullptr, nullptr, nullptr, nullptr, x, DM);

    // LN2 -> h2 splits
    ln_split_kernel<<<MT, 256>>>(attx, ln2w, ln2b, h2a, h2b);

    // FFN1 + bias + GELU -> ff1 splits
    gemmw<2><<<dim3(32, 32), 256, GSMEM>>>(h2a, h2b, w1a, w1b, 1024,
                                           nullptr, nullptr, nullptr, ff1a, ff1b, b1, nullptr, FF);

    // FFN2 + bias + residual(attx) -> d_out fp32
    gemmw<3><<<dim3(8, 32), 256, GSMEM>>>(ff1a, ff1b, w2a, w2b, FF,
                                          out, nullptr, nullptr, nullptr, nullptr, b2, attx, DM);
}

// round 7
// speedup vs baseline: 1.9263x; 1.1705x over previous
#include <cuda_runtime.h>
#include <cuda_bf16.h>
#include <mma.h>
#include <math.h>
#include <stdint.h>

typedef __nv_bfloat16 bf16;
using namespace nvcuda;

#define BB 2
#define SS 2048
#define DM 1024
#define NH 16
#define FF 4096
#define MT (BB*SS)   // 4096 rows

// ===================== packed f32x2 helpers (attention) =====================
union F2U { unsigned long long u; float2 f; };
__device__ __forceinline__ void fma2(F2U& d, const F2U a, const F2U b) {
    asm("fma.rn.f32x2 %0, %1, %2, %0;" : "+l"(d.u) : "l"(a.u), "l"(b.u));
}

// ===================== split helpers =====================
__device__ __forceinline__ void split2(float v, bf16& h, bf16& l) {
    h = __float2bfloat16(v);
    l = __float2bfloat16(v - __bfloat162float(h));
}
__device__ __forceinline__ uint32_t pkb(bf16 a, bf16 b) {
    unsigned short ua = __bfloat16_as_ushort(a), ub = __bfloat16_as_ushort(b);
    return (uint32_t)ua | ((uint32_t)ub << 16);
}

__device__ __forceinline__ uint32_t smem_to_u32(const void* p) {
    uint32_t a;
    asm("{ .reg .u64 tmp; cvta.to.shared.u64 tmp, %1; cvt.u32.u64 %0, tmp; }" : "=r"(a) : "l"(p));
    return a;
}
#define CP_ASYNC16(dst, src) \
    asm volatile("cp.async.cg.shared.global [%0], [%1], 16;" :: "r"(dst), "l"(src))
#define CP_COMMIT() asm volatile("cp.async.commit_group;" ::: "memory")
#define CP_WAIT1()  asm volatile("cp.async.wait_group 1;"  ::: "memory")
#define CP_WAIT0()  asm volatile("cp.async.wait_group 0;"  ::: "memory")

// ===================== scratch =====================
__device__ bf16 g_h1a[MT*DM],  g_h1b[MT*DM];
__device__ float g_q[MT*DM], g_k[MT*DM], g_v[MT*DM];
__device__ bf16 g_cata[MT*DM], g_catb[MT*DM];
__device__ float g_attx[MT*DM];
__device__ bf16 g_h2a[MT*DM],  g_h2b[MT*DM];
__device__ bf16 g_ff1a[(size_t)MT*FF], g_ff1b[(size_t)MT*FF];
__device__ bf16 g_Wqkva[3*DM*DM], g_Wqkvb[3*DM*DM];
__device__ bf16 g_Woa[DM*DM],  g_Wob[DM*DM];
__device__ bf16 g_W1a[DM*FF],  g_W1b[DM*FF];
__device__ bf16 g_W2a[DM*FF],  g_W2b[DM*FF];

// ===================== LayerNorm -> bf16 split pair =====================
__global__ void ln_split_kernel(const float* __restrict__ x, const float* __restrict__ w,
                                const float* __restrict__ b, bf16* __restrict__ o0, bf16* __restrict__ o1) {
    int row = blockIdx.x;
    int t = threadIdx.x;                       // 256 threads x 4 floats
    const float4* xr = (const float4*)(x + (size_t)row * DM);
    float4 v = xr[t];
    float s  = v.x + v.y + v.z + v.w;
    float ss = v.x*v.x + v.y*v.y + v.z*v.z + v.w*v.w;
    #pragma unroll
    for (int o = 16; o; o >>= 1) {
        s  += __shfl_xor_sync(0xffffffffu, s,  o);
        ss += __shfl_xor_sync(0xffffffffu, ss, o);
    }
    __shared__ float red[2][8];
    __shared__ float stats[2];
    int lane = t & 31, wid = t >> 5;
    if (lane == 0) { red[0][wid] = s; red[1][wid] = ss; }
    __syncthreads();
    if (t == 0) {
        float S1 = 0.f, S2 = 0.f;
        #pragma unroll
        for (int i = 0; i < 8; i++) { S1 += red[0][i]; S2 += red[1][i]; }
        float mu  = S1 * (1.f / DM);
        float var = S2 * (1.f / DM) - mu * mu;
        stats[0] = mu; stats[1] = rsqrtf(var + 1e-5f);
    }
    __syncthreads();
    float mu = stats[0], rs = stats[1];
    float4 wv = ((const float4*)w)[t];
    float4 bv = ((const float4*)b)[t];
    float y0 = (v.x - mu) * rs * wv.x + bv.x;
    float y1 = (v.y - mu) * rs * wv.y + bv.y;
    float y2 = (v.z - mu) * rs * wv.z + bv.z;
    float y3 = (v.w - mu) * rs * wv.w + bv.w;
    bf16 h0,l0,h1,l1,h2,l2,h3,l3;
    split2(y0,h0,l0); split2(y1,h1,l1); split2(y2,h2,l2); split2(y3,h3,l3);
    size_t idx = (size_t)row * DM + t * 4;
    *(uint2*)(o0 + idx) = make_uint2(pkb(h0,h1), pkb(h2,h3));
    *(uint2*)(o1 + idx) = make_uint2(pkb(l0,l1), pkb(l2,l3));
}

// ===================== transpose + split: out[c][r] = in[r][c] (bf16 hi/lo) =====================
__global__ void tsplit_kernel(const float* __restrict__ in, bf16* __restrict__ o0, bf16* __restrict__ o1,
                              int R, int C, size_t inBatch, size_t outBatch) {
    in += (size_t)blockIdx.z * inBatch;
    o0 += (size_t)blockIdx.z * outBatch;
    o1 += (size_t)blockIdx.z * outBatch;
    __shared__ float tile[32][33];
    int c0 = blockIdx.x * 32, r0 = blockIdx.y * 32;
    int tx = threadIdx.x, ty = threadIdx.y;   // (32, 8)
    #pragma unroll
    for (int i = 0; i < 4; i++)
        tile[ty + 8*i][tx] = in[(size_t)(r0 + ty + 8*i) * C + c0 + tx];
    __syncthreads();
    #pragma unroll
    for (int i = 0; i < 4; i++) {
        float v = tile[tx][ty + 8*i];
        bf16 h, l; split2(v, h, l);
        size_t oi = (size_t)(c0 + ty + 8*i) * R + r0 + tx;
        o0[oi] = h; o1[oi] = l;
    }
}

// ===================== wmma split-bf16 GEMM v2 =====================
// D[M,N] = (A0+A1)(B0+B1)^T ~= A0B0 + A0B1 + A1B0, fp32 accum.
// A row-major [M,K] bf16; B row-major [N,K] bf16 (col-major KxN view).
// CTA tile 128x128, 4 warps of 64x64, BK=32, 2-stage cp.async, 2 CTAs/SM.
// EPI: 0 = QKV scatter -> q/k/v [b,h,s,e] fp32
//      1 = +resid -> fp32 row-major
//      2 = +bias, exact GELU -> bf16 split pair
//      3 = +bias, +resid -> fp32 row-major
#define TILEB   10240              // one 128x32 bf16 tile, row pitch 80B
#define STAGEB  (4*TILEB)          // A0,A1,B0,B1
#define GSMEM   (2*STAGEB)         // 81920 B (>= 128*132*4 = 67584 epilogue)

template<int EPI>
__global__ __launch_bounds__(128, 2)
void gemmw(const bf16* __restrict__ A0, const bf16* __restrict__ A1,
           const bf16* __restrict__ B0, const bf16* __restrict__ B1, int K,
           float* __restrict__ out0, float* __restrict__ out1, float* __restrict__ out2,
           bf16* __restrict__ s0, bf16* __restrict__ s1,
           const float* __restrict__ bias, const float* __restrict__ resid, int N)
{
    extern __shared__ __align__(16) uint8_t smraw[];
    const uint32_t smb = smem_to_u32(smraw);
    const int tid = threadIdx.x;
    const int wid = tid >> 5;
    const int wm = wid >> 1, wn = wid & 1;     // 2 x 2 warp grid, 64x64 each
    const int m0 = blockIdx.y * 128;
    const int n0 = blockIdx.x * 128;

    const bf16* gsrc[4] = { A0 + (size_t)m0 * K, A1 + (size_t)m0 * K,
                            B0 + (size_t)n0 * K, B1 + (size_t)n0 * K };

    wmma::fragment<wmma::accumulator, 16, 16, 16, float> acc[4][4];
    #pragma unroll
    for (int i = 0; i < 4; i++)
        #pragma unroll
        for (int j = 0; j < 4; j++) wmma::fill_fragment(acc[i][j], 0.0f);

    const int NCH = K >> 5;

    // async load of chunk ch into stage st (4 tiles x 128 rows x 2 chunks16B... 4 per row)
    auto issue = [&](int ch, int st) {
        int k0 = ch << 5;
        #pragma unroll
        for (int i = 0; i < 16; i++) {
            int idx = i * 128 + tid;
            int t4  = idx >> 9;
            int rem = idx & 511;
            int row = rem >> 2;
            int cch = rem & 3;
            uint32_t dst = smb + st * STAGEB + t4 * TILEB + row * 80 + cch * 16;
            const bf16* src = gsrc[t4] + (size_t)row * K + k0 + cch * 8;
            CP_ASYNC16(dst, src);
        }
        CP_COMMIT();
    };

    issue(0, 0);

    for (int ch = 0; ch < NCH; ch++) {
        if (ch + 1 < NCH) { issue(ch + 1, (ch + 1) & 1); CP_WAIT1(); }
        else              { CP_WAIT0(); }
        __syncthreads();
        const int st = ch & 1;
        const bf16* As0 = (const bf16*)(smraw + st * STAGEB);
        const bf16* As1 = (const bf16*)(smraw + st * STAGEB + TILEB);
        const bf16* Bs0 = (const bf16*)(smraw + st * STAGEB + 2 * TILEB);
        const bf16* Bs1 = (const bf16*)(smraw + st * STAGEB + 3 * TILEB);
        #pragma unroll
        for (int kk = 0; kk < 32; kk += 16) {
            wmma::fragment<wmma::matrix_a, 16, 16, 16, bf16, wmma::row_major> a0[4], a1[4];
            #pragma unroll
            for (int i = 0; i < 4; i++) {
                wmma::load_matrix_sync(a0[i], As0 + (wm * 64 + i * 16) * 40 + kk, 40);
                wmma::load_matrix_sync(a1[i], As1 + (wm * 64 + i * 16) * 40 + kk, 40);
            }
            #pragma unroll
            for (int j = 0; j < 4; j++) {
                wmma::fragment<wmma::matrix_b, 16, 16, 16, bf16, wmma::col_major> b0, b1;
                wmma::load_matrix_sync(b0, Bs0 + (wn * 64 + j * 16) * 40 + kk, 40);
                wmma::load_matrix_sync(b1, Bs1 + (wn * 64 + j * 16) * 40 + kk, 40);
                #pragma unroll
                for (int i = 0; i < 4; i++) {
                    wmma::mma_sync(acc[i][j], a0[i], b0, acc[i][j]);
                    wmma::mma_sync(acc[i][j], a0[i], b1, acc[i][j]);
                    wmma::mma_sync(acc[i][j], a1[i], b0, acc[i][j]);
                }
            }
        }
        __syncthreads();
    }

    // ---- epilogue through smem for coalesced writes ----
    float* Cs = (float*)smraw;        // [128][132]
    #pragma unroll
    for (int i = 0; i < 4; i++)
        #pragma unroll
        for (int j = 0; j < 4; j++)
            wmma::store_matrix_sync(Cs + (wm * 64 + i * 16) * 132 + (wn * 64 + j * 16),
                                    acc[i][j], 132, wmma::mem_row_major);
    __syncthreads();

    #pragma unroll
    for (int it = 0; it < 32; it++) {
        int idx = it * 128 + tid;
        int r  = idx >> 5;
        int c4 = (idx & 31) << 2;
        float4 vv = *(const float4*)(Cs + r * 132 + c4);
        int row = m0 + r;
        int c   = n0 + c4;
        if (EPI == 0) {
            int b = row >> 11, sq = row & 2047;
            int proj = c >> 10, cc = c & 1023, hh = cc >> 6, e0 = cc & 63;
            float* base = (proj == 0) ? out0 : (proj == 1) ? out1 : out2;
            *(float4*)(base + ((size_t)(b * NH + hh) * SS + sq) * 64 + e0) = vv;
        } else if (EPI == 1) {
            float4 r4 = *(const float4*)(resid + (size_t)row * N + c);
            vv.x += r4.x; vv.y += r4.y; vv.z += r4.z; vv.w += r4.w;
            *(float4*)(out0 + (size_t)row * N + c) = vv;
        } else if (EPI == 2) {
            float4 b4 = *(const float4*)(bias + c);
            float o[4] = {vv.x + b4.x, vv.y + b4.y, vv.z + b4.z, vv.w + b4.w};
            #pragma unroll
            for (int u = 0; u < 4; u++) o[u] = 0.5f * o[u] * (1.f + erff(o[u] * 0.70710678118f));
            bf16 h0,l0,h1,l1,h2,l2,h3,l3;
            split2(o[0],h0,l0); split2(o[1],h1,l1); split2(o[2],h2,l2); split2(o[3],h3,l3);
            size_t base = (size_t)row * N + c;
            *(uint2*)(s0 + base) = make_uint2(pkb(h0,h1), pkb(h2,h3));
            *(uint2*)(s1 + base) = make_uint2(pkb(l0,l1), pkb(l2,l3));
        } else {  // EPI == 3
            float4 b4 = *(const float4*)(bias + c);
            float4 r4 = *(const float4*)(resid + (size_t)row * N + c);
            vv.x += b4.x + r4.x; vv.y += b4.y + r4.y;
            vv.z += b4.z + r4.z; vv.w += b4.w + r4.w;
            *(float4*)(out0 + (size_t)row * N + c) = vv;
        }
    }
}

// ===================== causal flash attention (fp32, f32x2), writes bf16 split concat =====================
__global__ void attn_kernel(const float* __restrict__ Q, const float* __restrict__ Kg,
                            const float* __restrict__ Vg,
                            bf16* __restrict__ O0, bf16* __restrict__ O1)
{
    __shared__ __align__(16) float KV[64][64];
    __shared__ float sc[64][65];
    int t  = threadIdx.x;
    int qt = blockIdx.x;
    int bh = blockIdx.y;
    int qi = qt * 64 + t;

    const float* qrow = Q + ((size_t)bh * SS + qi) * 64;
    F2U qp[32];
    #pragma unroll
    for (int e = 0; e < 32; e += 2) {
        float4 f = *(const float4*)(qrow + 2 * e);
        qp[e].f     = make_float2(f.x, f.y);
        qp[e + 1].f = make_float2(f.z, f.w);
    }
    F2U accp[32];
    #pragma unroll
    for (int e = 0; e < 32; e++) accp[e].u = 0ull;
    float m = -INFINITY, l = 0.f;

    for (int kt = 0; kt <= qt; kt++) {
        int k0 = kt * 64;
        __syncthreads();
        const float* kb = Kg + ((size_t)bh * SS + k0) * 64;
        for (int i = t; i < 64 * 16; i += 64) {
            int r = i >> 4, c = (i & 15) << 2;
            *(float4*)&KV[r][c] = *(const float4*)(kb + r * 64 + c);
        }
        __syncthreads();

        float tmax = -INFINITY;
        for (int j = 0; j < 64; j++) {
            const F2U* kr = (const F2U*)KV[j];
            F2U s2; s2.u = 0ull;
            #pragma unroll
            for (int e = 0; e < 32; e++) fma2(s2, qp[e], kr[e]);
            float s = (s2.f.x + s2.f.y) * 0.125f;
            if (k0 + j > qi) s = -INFINITY;
            sc[t][j] = s;
            tmax = fmaxf(tmax, s);
        }
        float nm   = fmaxf(m, tmax);
        float corr = __expf(m - nm);
        l *= corr;
        #pragma unroll
        for (int e = 0; e < 32; e++) { accp[e].f.x *= corr; accp[e].f.y *= corr; }

        __syncthreads();
        const float* vb = Vg + ((size_t)bh * SS + k0) * 64;
        for (int i = t; i < 64 * 16; i += 64) {
            int r = i >> 4, c = (i & 15) << 2;
            *(float4*)&KV[r][c] = *(const float4*)(vb + r * 64 + c);
        }
        __syncthreads();

        for (int j = 0; j < 64; j++) {
            float p = __expf(sc[t][j] - nm);
            l += p;
            F2U pd; pd.f = make_float2(p, p);
            const F2U* vr = (const F2U*)KV[j];
            #pragma unroll
            for (int e = 0; e < 32; e++) fma2(accp[e], pd, vr[e]);
        }
        m = nm;
    }

    float inv = 1.f / l;
    int b = bh >> 4, hh = bh & 15;
    size_t base = ((size_t)(b * SS + qi)) * DM + hh * 64;
    #pragma unroll
    for (int e = 0; e < 32; e++) {
        float v0 = accp[e].f.x * inv, v1 = accp[e].f.y * inv;
        bf16 h0,l0,h1,l1;
        split2(v0,h0,l0); split2(v1,h1,l1);
        *(uint32_t*)(O0 + base + 2*e) = pkb(h0,h1);
        *(uint32_t*)(O1 + base + 2*e) = pkb(l0,l1);
    }
}

// ===================== launch =====================
extern "C" void kernel_launch(void* const* d_in, const int* in_sizes, int n_in,
                              void* d_out, int out_size) {
    const float* x    = (const float*)d_in[0];
    const float* Wq   = (const float*)d_in[2];
    const float* Wk   = (const float*)d_in[3];
    const float* Wv   = (const float*)d_in[4];
    const float* Wo   = (const float*)d_in[5];
    const float* ln1w = (const float*)d_in[6];
    const float* ln1b = (const float*)d_in[7];
    const float* ln2w = (const float*)d_in[8];
    const float* ln2b = (const float*)d_in[9];
    const float* W1   = (const float*)d_in[10];
    const float* b1   = (const float*)d_in[11];
    const float* W2   = (const float*)d_in[12];
    const float* b2   = (const float*)d_in[13];
    float* out = (float*)d_out;

    bf16 *h1a,*h1b,*cata,*catb,*h2a,*h2b,*ff1a,*ff1b;
    bf16 *wqkva,*wqkvb,*woa,*wob,*w1a,*w1b,*w2a,*w2b;
    float *q,*k,*v,*attx;
    cudaGetSymbolAddress((void**)&h1a, g_h1a);   cudaGetSymbolAddress((void**)&h1b, g_h1b);
    cudaGetSymbolAddress((void**)&q, g_q);       cudaGetSymbolAddress((void**)&k, g_k);
    cudaGetSymbolAddress((void**)&v, g_v);
    cudaGetSymbolAddress((void**)&cata, g_cata); cudaGetSymbolAddress((void**)&catb, g_catb);
    cudaGetSymbolAddress((void**)&attx, g_attx);
    cudaGetSymbolAddress((void**)&h2a, g_h2a);   cudaGetSymbolAddress((void**)&h2b, g_h2b);
    cudaGetSymbolAddress((void**)&ff1a, g_ff1a); cudaGetSymbolAddress((void**)&ff1b, g_ff1b);
    cudaGetSymbolAddress((void**)&wqkva, g_Wqkva); cudaGetSymbolAddress((void**)&wqkvb, g_Wqkvb);
    cudaGetSymbolAddress((void**)&woa, g_Woa);   cudaGetSymbolAddress((void**)&wob, g_Wob);
    cudaGetSymbolAddress((void**)&w1a, g_W1a);   cudaGetSymbolAddress((void**)&w1b, g_W1b);
    cudaGetSymbolAddress((void**)&w2a, g_W2a);   cudaGetSymbolAddress((void**)&w2b, g_W2b);

    cudaFuncSetAttribute(gemmw<0>, cudaFuncAttributeMaxDynamicSharedMemorySize, GSMEM);
    cudaFuncSetAttribute(gemmw<1>, cudaFuncAttributeMaxDynamicSharedMemorySize, GSMEM);
    cudaFuncSetAttribute(gemmw<2>, cudaFuncAttributeMaxDynamicSharedMemorySize, GSMEM);
    cudaFuncSetAttribute(gemmw<3>, cudaFuncAttributeMaxDynamicSharedMemorySize, GSMEM);

    dim3 t32x8(32, 8);

    // LN1 -> h1 splits
    ln_split_kernel<<<MT, 256>>>(x, ln1w, ln1b, h1a, h1b);

    // weight transpose + split (B layout: [N,K] bf16 hi/lo)
    tsplit_kernel<<<dim3(2, 32, 16), t32x8>>>(Wq, wqkva,               wqkvb,               1024, 64, (size_t)1024*64, (size_t)64*1024);
    tsplit_kernel<<<dim3(2, 32, 16), t32x8>>>(Wk, wqkva + 1024*1024,   wqkvb + 1024*1024,   1024, 64, (size_t)1024*64, (size_t)64*1024);
    tsplit_kernel<<<dim3(2, 32, 16), t32x8>>>(Wv, wqkva + 2*1024*1024, wqkvb + 2*1024*1024, 1024, 64, (size_t)1024*64, (size_t)64*1024);
    tsplit_kernel<<<dim3(32, 32, 1),  t32x8>>>(Wo, woa, wob, 1024, 1024, 0, 0);
    tsplit_kernel<<<dim3(128, 32, 1), t32x8>>>(W1, w1a, w1b, 1024, 4096, 0, 0);
    tsplit_kernel<<<dim3(32, 128, 1), t32x8>>>(W2, w2a, w2b, 4096, 1024, 0, 0);

    // QKV fused GEMM: M=4096, N=3072, K=1024 -> q/k/v fp32 [b,h,s,e]
    gemmw<0><<<dim3(24, 32), 128, GSMEM>>>(h1a, h1b, wqkva, wqkvb, 1024,
                                           q, k, v, nullptr, nullptr, nullptr, nullptr, 0);

    // causal attention -> concat bf16 splits
    attn_kernel<<<dim3(SS / 64, BB * NH), 64>>>(q, k, v, cata, catb);

    // Wo + residual(x) -> attx fp32
    gemmw<1><<<dim3(8, 32), 128, GSMEM>>>(cata, catb, woa, wob, 1024,
                                          attx, nullptr, nullptr, nullptr, nullptr, nullptr, x, DM);

    // LN2 -> h2 splits
    ln_split_kernel<<<MT, 256>>>(attx, ln2w, ln2b, h2a, h2b);

    // FFN1 + bias + GELU -> ff1 splits
    gemmw<2><<<dim3(32, 32), 128, GSMEM>>>(h2a, h2b, w1a, w1b, 1024,
                                           nullptr, nullptr, nullptr, ff1a, ff1b, b1, nullptr, FF);

    // FFN2 + bias + residual(attx) -> d_out fp32
    gemmw<3><<<dim3(8, 32), 128, GSMEM>>>(ff1a, ff1b, w2a, w2b, FF,
                                          out, nullptr, nullptr, nullptr, nullptr, b2, attx, DM);
}